// round 4
// baseline (speedup 1.0000x reference)
#include <cuda_runtime.h>
#include <cstdint>

#define N_NODES 100000
#define N_EDGES 1600000
#define D 128          // D_IN == D_OUT == 128

#define SCAN_BLK 512
#define NB_SCAN ((N_NODES + SCAN_BLK - 1) / SCAN_BLK)   // 196

// ---- device-global scratch (allocation-free rule) ----
__device__ float g_support[(size_t)N_NODES * D];   // 51.2 MB
__device__ int   g_counts[N_NODES];
__device__ int   g_rowstart[N_NODES + 1];
__device__ int   g_cur[N_NODES];
__device__ int   g_sums[NB_SCAN];
__device__ int   g_offsets[NB_SCAN];
__device__ int   g_ccol[N_EDGES];                  // 6.4 MB
__device__ float g_cval[N_EDGES];                  // 6.4 MB

// ---- side stream + events for fork-join under graph capture.
// Created in a global constructor: before the harness's first memory
// checkpoint, once per process, no per-call resource creation.
struct StreamInit {
    cudaStream_t s2;
    cudaEvent_t ev_fork, ev_join;
    StreamInit() {
        cudaStreamCreateWithFlags(&s2, cudaStreamNonBlocking);
        cudaEventCreateWithFlags(&ev_fork, cudaEventDisableTiming);
        cudaEventCreateWithFlags(&ev_join, cudaEventDisableTiming);
    }
};
static StreamInit g_si;

// ---------------------------------------------------------------------------
// 0) zero the per-row edge counters (every call / graph replay)
// ---------------------------------------------------------------------------
__global__ void zero_counts_kernel() {
    int i = blockIdx.x * blockDim.x + threadIdx.x;
    if (i < N_NODES) g_counts[i] = 0;
}

// ---------------------------------------------------------------------------
// 1) GEMM v2: support = x @ W + b
//    64 rows x 128 cols per block, KT=32.
//    lane owns cols {lane, lane+32, lane+64, lane+96}  (conflict-free W reads)
//    accumulators packed over ROW PAIRS via fma.rn.f32x2; the packed
//    (a_r, a_{r+1}) operand comes straight from a transposed x-tile (LDS.64
//    broadcast), and W is pre-duplicated in smem as float2(w,w):
//    hot loop = 16 FFMA2 + 8 LDS.64 per k per thread, zero MOV packs.
// ---------------------------------------------------------------------------
#define ROWS_PER_BLK 64
#define KT 32
#define XS_STRIDE 66   // even stride: keeps row-pair LDS.64 8B-aligned

__device__ __forceinline__ void fma_f32x2(unsigned long long& d,
                                          unsigned long long a,
                                          unsigned long long b) {
    asm("fma.rn.f32x2 %0, %1, %2, %0;" : "+l"(d) : "l"(a), "l"(b));
}

__device__ __forceinline__ unsigned long long pack_ff(float lo, float hi) {
    unsigned long long r;
    asm("mov.b64 %0, {%1, %2};" : "=l"(r) : "f"(lo), "f"(hi));
    return r;
}

__global__ __launch_bounds__(256, 2) void gemm_bias_kernel(
    const float* __restrict__ x, const float* __restrict__ W,
    const float* __restrict__ b, float* __restrict__ sup) {
    __shared__ float xs[KT][XS_STRIDE];            // transposed x tile
    __shared__ float2 wsp[KT][D];                  // duplicated W tile (32KB)

    const int tid  = threadIdx.x;
    const int lane = tid & 31;
    const int rg   = tid >> 5;                     // warp -> 8-row group
    const int row0 = blockIdx.x * ROWS_PER_BLK;

    // acc[p][j]: rows (rg*8+2p, rg*8+2p+1) x col (lane+32j), packed over rows
    unsigned long long acc[4][4];
#pragma unroll
    for (int j = 0; j < 4; j++) {
        const float bj = b[lane + 32 * j];
        const unsigned long long bb = pack_ff(bj, bj);
#pragma unroll
        for (int p = 0; p < 4; p++) acc[p][j] = bb;
    }

    for (int kt = 0; kt < D; kt += KT) {
        __syncthreads();
        // stage x transposed: xs[k][r] = x[row0+r][kt+k]; reads coalesced
#pragma unroll
        for (int j = 0; j < 8; j++) {
            int idx = tid + j * 256;               // 0..2047
            int r = idx >> 5, k = idx & 31;
            int grow = row0 + r;
            xs[k][r] = (grow < N_NODES) ? x[(size_t)grow * D + kt + k] : 0.f;
        }
        // stage W duplicated: wsp[k][c] = (w, w); reads & stores coalesced
#pragma unroll
        for (int j = 0; j < 16; j++) {
            int idx = tid + j * 256;               // 0..4095
            int k = idx >> 7, c = idx & 127;
            float w = W[(size_t)(kt + k) * D + c];
            wsp[k][c] = make_float2(w, w);
        }
        __syncthreads();

#pragma unroll 4
        for (int k = 0; k < KT; k++) {
            unsigned long long ap[4];
#pragma unroll
            for (int p = 0; p < 4; p++)            // broadcast LDS.64
                ap[p] = *reinterpret_cast<const unsigned long long*>(
                    &xs[k][rg * 8 + 2 * p]);
#pragma unroll
            for (int j = 0; j < 4; j++) {          // conflict-free LDS.64
                const unsigned long long wp =
                    *reinterpret_cast<const unsigned long long*>(
                        &wsp[k][lane + 32 * j]);
#pragma unroll
                for (int p = 0; p < 4; p++) fma_f32x2(acc[p][j], ap[p], wp);
            }
        }
    }

    // epilogue: unpack row pairs, coalesced scalar stores
#pragma unroll
    for (int p = 0; p < 4; p++) {
        const int r0 = row0 + rg * 8 + 2 * p;
#pragma unroll
        for (int j = 0; j < 4; j++) {
            float2 v = *reinterpret_cast<float2*>(&acc[p][j]);
            const int c = lane + 32 * j;
            if (r0 < N_NODES)     sup[(size_t)r0 * D + c]       = v.x;
            if (r0 + 1 < N_NODES) sup[(size_t)(r0 + 1) * D + c] = v.y;
        }
    }
}

// ---------------------------------------------------------------------------
// 2) histogram of destination rows
// ---------------------------------------------------------------------------
__global__ void hist_kernel(const int* __restrict__ rows) {
    int e = blockIdx.x * blockDim.x + threadIdx.x;
    if (e < N_EDGES) atomicAdd(&g_counts[rows[e]], 1);
}

// ---------------------------------------------------------------------------
// 3a) per-block reduction of counts
// ---------------------------------------------------------------------------
__global__ void reduce_kernel() {
    __shared__ int sh[SCAN_BLK];
    int g = blockIdx.x * SCAN_BLK + threadIdx.x;
    sh[threadIdx.x] = (g < N_NODES) ? g_counts[g] : 0;
    __syncthreads();
#pragma unroll
    for (int s = SCAN_BLK / 2; s > 0; s >>= 1) {
        if (threadIdx.x < s) sh[threadIdx.x] += sh[threadIdx.x + s];
        __syncthreads();
    }
    if (threadIdx.x == 0) g_sums[blockIdx.x] = sh[0];
}

// 3b) exclusive scan of the 196 block sums (single block)
__global__ void scan_sums_kernel() {
    __shared__ int sh[NB_SCAN];
    int t = threadIdx.x;
    for (int i = t; i < NB_SCAN; i += blockDim.x) sh[i] = g_sums[i];
    __syncthreads();
    if (t == 0) {
        int run = 0;
        for (int i = 0; i < NB_SCAN; i++) { int v = sh[i]; sh[i] = run; run += v; }
    }
    __syncthreads();
    for (int i = t; i < NB_SCAN; i += blockDim.x) g_offsets[i] = sh[i];
}

// 3c) per-block exclusive scan + global offset -> row_start, cur
__global__ void scan_block_kernel() {
    __shared__ int sh[SCAN_BLK];
    int tid = threadIdx.x;
    int g = blockIdx.x * SCAN_BLK + tid;
    int v = (g < N_NODES) ? g_counts[g] : 0;
    sh[tid] = v;
    __syncthreads();
#pragma unroll
    for (int d = 1; d < SCAN_BLK; d <<= 1) {
        int t = (tid >= d) ? sh[tid - d] : 0;
        __syncthreads();
        sh[tid] += t;
        __syncthreads();
    }
    int incl = sh[tid];
    int excl = incl - v;
    int base = g_offsets[blockIdx.x];
    if (g < N_NODES) {
        int s = base + excl;
        g_rowstart[g] = s;
        g_cur[g] = s;
        if (g == N_NODES - 1) g_rowstart[N_NODES] = base + incl;
    }
}

// ---------------------------------------------------------------------------
// 4) scatter edges into CSR slots
// ---------------------------------------------------------------------------
__global__ void fill_kernel(const int* __restrict__ rows,
                            const int* __restrict__ cols,
                            const float* __restrict__ vals) {
    int e = blockIdx.x * blockDim.x + threadIdx.x;
    if (e < N_EDGES) {
        int r = rows[e];
        int pos = atomicAdd(&g_cur[r], 1);
        g_ccol[pos] = cols[e];
        g_cval[pos] = vals[e];
    }
}

// ---------------------------------------------------------------------------
// 5) SpMM: one warp per output row, gather-only, register accumulate,
//          single coalesced store (no atomics, no output zeroing needed).
// ---------------------------------------------------------------------------
__global__ __launch_bounds__(256) void spmm_kernel(float* __restrict__ out) {
    const int warp = (blockIdx.x * blockDim.x + threadIdx.x) >> 5;
    const int lane = threadIdx.x & 31;
    if (warp >= N_NODES) return;

    const int s = __ldg(&g_rowstart[warp]);
    const int e = __ldg(&g_rowstart[warp + 1]);

    const float4* sup4 = reinterpret_cast<const float4*>(g_support);
    float4 acc = make_float4(0.f, 0.f, 0.f, 0.f);

    int i = s;
    for (; i + 1 < e; i += 2) {
        int   c0 = __ldg(&g_ccol[i]);
        int   c1 = __ldg(&g_ccol[i + 1]);
        float v0 = __ldg(&g_cval[i]);
        float v1 = __ldg(&g_cval[i + 1]);
        float4 s0 = sup4[(size_t)c0 * (D / 4) + lane];
        float4 s1 = sup4[(size_t)c1 * (D / 4) + lane];
        acc.x += s0.x * v0; acc.y += s0.y * v0;
        acc.z += s0.z * v0; acc.w += s0.w * v0;
        acc.x += s1.x * v1; acc.y += s1.y * v1;
        acc.z += s1.z * v1; acc.w += s1.w * v1;
    }
    if (i < e) {
        int   c = __ldg(&g_ccol[i]);
        float v = __ldg(&g_cval[i]);
        float4 s0 = sup4[(size_t)c * (D / 4) + lane];
        acc.x += s0.x * v; acc.y += s0.y * v;
        acc.z += s0.z * v; acc.w += s0.w * v;
    }
    reinterpret_cast<float4*>(out)[(size_t)warp * (D / 4) + lane] = acc;
}

// ---------------------------------------------------------------------------
// Launch.  Inputs: x, rows, cols, vals, W, b.  Output: f32 [N_NODES, D].
// Fork-join: CSR build chain on side stream, GEMM on capture stream,
// SpMM after join.
// ---------------------------------------------------------------------------
extern "C" void kernel_launch(void* const* d_in, const int* in_sizes, int n_in,
                              void* d_out, int out_size) {
    const float* x    = (const float*)d_in[0];
    const int*   rows = (const int*)d_in[1];
    const int*   cols = (const int*)d_in[2];
    const float* vals = (const float*)d_in[3];
    const float* W    = (const float*)d_in[4];
    const float* b    = (const float*)d_in[5];
    float* out = (float*)d_out;

    float* sup = nullptr;
    cudaGetSymbolAddress((void**)&sup, g_support);

    // fork side stream off the (captured) default stream
    cudaEventRecord(g_si.ev_fork, 0);
    cudaStreamWaitEvent(g_si.s2, g_si.ev_fork, 0);

    // --- CSR build chain on side stream ---
    zero_counts_kernel<<<(N_NODES + 255) / 256, 256, 0, g_si.s2>>>();
    hist_kernel<<<(N_EDGES + 255) / 256, 256, 0, g_si.s2>>>(rows);
    reduce_kernel<<<NB_SCAN, SCAN_BLK, 0, g_si.s2>>>();
    scan_sums_kernel<<<1, 256, 0, g_si.s2>>>();
    scan_block_kernel<<<NB_SCAN, SCAN_BLK, 0, g_si.s2>>>();
    fill_kernel<<<(N_EDGES + 255) / 256, 256, 0, g_si.s2>>>(rows, cols, vals);
    cudaEventRecord(g_si.ev_join, g_si.s2);

    // --- GEMM on the capture stream (overlaps CSR chain) ---
    gemm_bias_kernel<<<(N_NODES + ROWS_PER_BLK - 1) / ROWS_PER_BLK, 256>>>(
        x, W, b, sup);

    // --- join, then SpMM ---
    cudaStreamWaitEvent(0, g_si.ev_join, 0);
    {
        long long total_threads = (long long)N_NODES * 32;
        int blk = 256;
        int grid = (int)((total_threads + blk - 1) / blk);
        spmm_kernel<<<grid, blk>>>(out);
    }
}

// round 5
// speedup vs baseline: 1.0664x; 1.0664x over previous
#include <cuda_runtime.h>
#include <cuda_fp16.h>
#include <cstdint>

#define N_NODES 100000
#define N_EDGES 1600000
#define D 128          // D_IN == D_OUT == 128

#define SCAN_BLK 512
#define NB_SCAN ((N_NODES + SCAN_BLK - 1) / SCAN_BLK)   // 196

// ---- device-global scratch (allocation-free rule) ----
__device__ __half g_supph[(size_t)N_NODES * D];    // 25.6 MB (fp16 support)
__device__ int    g_counts[N_NODES];
__device__ int    g_rowstart[N_NODES + 1];
__device__ int    g_cur[N_NODES];
__device__ int    g_sums[NB_SCAN];
__device__ int    g_offsets[NB_SCAN];
__device__ int2   g_edge[N_EDGES];                 // 12.8 MB {col, val bits}

// ---------------------------------------------------------------------------
// 0) zero the per-row edge counters (every call / graph replay)
// ---------------------------------------------------------------------------
__global__ void zero_counts_kernel() {
    int i = blockIdx.x * blockDim.x + threadIdx.x;
    if (i < N_NODES) g_counts[i] = 0;
}

// ---------------------------------------------------------------------------
// 1) GEMM v3: support = x @ W + b, stored as fp16.
//    Block: 128 rows x 128 cols, 256 threads (8 warps x 16 rows).
//    Thread: 16 rows x 4 cols, accumulators packed over row pairs (f32x2).
//    Per k per thread: 8 broadcast LDS.64 (crossbar-free) + 4 LDS.32 +
//    4 MOV packs + 32 FFMA2  ->  FMA-issue-bound.
// ---------------------------------------------------------------------------
#define GR 128        // rows per block
#define KT 32
#define XS_STRIDE 130 // even stride: row-pair LDS.64 stays 8B-aligned

__device__ __forceinline__ void fma_f32x2(unsigned long long& d,
                                          unsigned long long a,
                                          unsigned long long b) {
    asm("fma.rn.f32x2 %0, %1, %2, %0;" : "+l"(d) : "l"(a), "l"(b));
}

__device__ __forceinline__ unsigned long long pack_ff(float lo, float hi) {
    unsigned long long r;
    asm("mov.b64 %0, {%1, %2};" : "=l"(r) : "f"(lo), "f"(hi));
    return r;
}

__global__ __launch_bounds__(256, 2) void gemm_bias_kernel(
    const float* __restrict__ x, const float* __restrict__ W,
    const float* __restrict__ b, __half* __restrict__ suph) {
    __shared__ float xs[KT][XS_STRIDE];   // transposed x tile [k][r]
    __shared__ float ws[KT][D];           // W tile

    const int tid  = threadIdx.x;
    const int lane = tid & 31;
    const int wid  = tid >> 5;            // warp -> 16-row group
    const int row0 = blockIdx.x * GR;

    // acc[p][j]: rows (wid*16+2p, +1) x col (lane+32j), packed over the rows
    unsigned long long acc[8][4];
#pragma unroll
    for (int j = 0; j < 4; j++) {
        const float bj = b[lane + 32 * j];
        const unsigned long long bb = pack_ff(bj, bj);
#pragma unroll
        for (int p = 0; p < 8; p++) acc[p][j] = bb;
    }

    for (int kt = 0; kt < D; kt += KT) {
        __syncthreads();
        // stage x transposed: 128 rows x 32 k -> 16 elems/thread, coalesced
#pragma unroll
        for (int j = 0; j < 16; j++) {
            int idx = tid + j * 256;               // 0..4095
            int r = idx >> 5, k = idx & 31;
            int grow = row0 + r;
            xs[k][r] = (grow < N_NODES) ? x[(size_t)grow * D + kt + k] : 0.f;
        }
        // stage W: 32 k x 128 c as float4, conflict-free
#pragma unroll
        for (int j = 0; j < 4; j++) {
            int idx = tid + j * 256;               // float4 idx 0..1023
            int k = idx >> 5, c4 = idx & 31;
            reinterpret_cast<float4*>(&ws[k][0])[c4] =
                reinterpret_cast<const float4*>(&W[(size_t)(kt + k) * D])[c4];
        }
        __syncthreads();

#pragma unroll 4
        for (int k = 0; k < KT; k++) {
            unsigned long long ap[8];
#pragma unroll
            for (int p = 0; p < 8; p++)            // broadcast LDS.64
                ap[p] = *reinterpret_cast<const unsigned long long*>(
                    &xs[k][wid * 16 + 2 * p]);
            unsigned long long wp[4];
#pragma unroll
            for (int j = 0; j < 4; j++) {          // conflict-free LDS.32
                const float w = ws[k][lane + 32 * j];
                wp[j] = pack_ff(w, w);
            }
#pragma unroll
            for (int p = 0; p < 8; p++)
#pragma unroll
                for (int j = 0; j < 4; j++) fma_f32x2(acc[p][j], ap[p], wp[j]);
        }
    }

    // epilogue: unpack row pairs, convert to fp16, store
#pragma unroll
    for (int p = 0; p < 8; p++) {
        const int r0 = row0 + wid * 16 + 2 * p;
#pragma unroll
        for (int j = 0; j < 4; j++) {
            float2 v = *reinterpret_cast<float2*>(&acc[p][j]);
            const int c = lane + 32 * j;
            if (r0 < N_NODES)     suph[(size_t)r0 * D + c]       = __float2half(v.x);
            if (r0 + 1 < N_NODES) suph[(size_t)(r0 + 1) * D + c] = __float2half(v.y);
        }
    }
}

// ---------------------------------------------------------------------------
// 2) histogram of destination rows
// ---------------------------------------------------------------------------
__global__ void hist_kernel(const int* __restrict__ rows) {
    int e = blockIdx.x * blockDim.x + threadIdx.x;
    if (e < N_EDGES) atomicAdd(&g_counts[rows[e]], 1);
}

// ---------------------------------------------------------------------------
// 3a) per-block reduction of counts
// ---------------------------------------------------------------------------
__global__ void reduce_kernel() {
    __shared__ int sh[SCAN_BLK];
    int g = blockIdx.x * SCAN_BLK + threadIdx.x;
    sh[threadIdx.x] = (g < N_NODES) ? g_counts[g] : 0;
    __syncthreads();
#pragma unroll
    for (int s = SCAN_BLK / 2; s > 0; s >>= 1) {
        if (threadIdx.x < s) sh[threadIdx.x] += sh[threadIdx.x + s];
        __syncthreads();
    }
    if (threadIdx.x == 0) g_sums[blockIdx.x] = sh[0];
}

// 3b) exclusive scan of the 196 block sums (single block, parallel)
__global__ void scan_sums_kernel() {
    __shared__ int sh[256];
    int t = threadIdx.x;
    int v = (t < NB_SCAN) ? g_sums[t] : 0;
    sh[t] = v;
    __syncthreads();
#pragma unroll
    for (int d = 1; d < 256; d <<= 1) {
        int tv = (t >= d) ? sh[t - d] : 0;
        __syncthreads();
        sh[t] += tv;
        __syncthreads();
    }
    if (t < NB_SCAN) g_offsets[t] = sh[t] - v;   // exclusive
}

// 3c) per-block exclusive scan + global offset -> row_start, cur
__global__ void scan_block_kernel() {
    __shared__ int sh[SCAN_BLK];
    int tid = threadIdx.x;
    int g = blockIdx.x * SCAN_BLK + tid;
    int v = (g < N_NODES) ? g_counts[g] : 0;
    sh[tid] = v;
    __syncthreads();
#pragma unroll
    for (int d = 1; d < SCAN_BLK; d <<= 1) {
        int t = (tid >= d) ? sh[tid - d] : 0;
        __syncthreads();
        sh[tid] += t;
        __syncthreads();
    }
    int incl = sh[tid];
    int excl = incl - v;
    int base = g_offsets[blockIdx.x];
    if (g < N_NODES) {
        int s = base + excl;
        g_rowstart[g] = s;
        g_cur[g] = s;
        if (g == N_NODES - 1) g_rowstart[N_NODES] = base + incl;
    }
}

// ---------------------------------------------------------------------------
// 4) scatter edges into CSR slots (packed {col, val} -> one 8B store)
// ---------------------------------------------------------------------------
__global__ void fill_kernel(const int* __restrict__ rows,
                            const int* __restrict__ cols,
                            const float* __restrict__ vals) {
    int e = blockIdx.x * blockDim.x + threadIdx.x;
    if (e < N_EDGES) {
        int r = rows[e];
        int pos = atomicAdd(&g_cur[r], 1);
        g_edge[pos] = make_int2(cols[e], __float_as_int(vals[e]));
    }
}

// ---------------------------------------------------------------------------
// 5) SpMM: one warp per output row, fp16 gathers (256B/row), fp32 accumulate,
//          single coalesced float4 store. No atomics, no output zeroing.
//          Lane owns output cols [4*lane, 4*lane+4).
// ---------------------------------------------------------------------------
__global__ __launch_bounds__(256) void spmm_kernel(float* __restrict__ out) {
    const int row  = (blockIdx.x * blockDim.x + threadIdx.x) >> 5;
    const int lane = threadIdx.x & 31;
    if (row >= N_NODES) return;

    const int s = __ldg(&g_rowstart[row]);
    const int e = __ldg(&g_rowstart[row + 1]);

    float4 acc = make_float4(0.f, 0.f, 0.f, 0.f);

    int i = s;
    for (; i + 1 < e; i += 2) {
        int2 e0 = g_edge[i];
        int2 e1 = g_edge[i + 1];
        float v0 = __int_as_float(e0.y);
        float v1 = __int_as_float(e1.y);
        uint2 h0 = *reinterpret_cast<const uint2*>(
            &g_supph[(size_t)e0.x * D + lane * 4]);
        uint2 h1 = *reinterpret_cast<const uint2*>(
            &g_supph[(size_t)e1.x * D + lane * 4]);
        float2 a0 = __half22float2(*reinterpret_cast<__half2*>(&h0.x));
        float2 b0 = __half22float2(*reinterpret_cast<__half2*>(&h0.y));
        float2 a1 = __half22float2(*reinterpret_cast<__half2*>(&h1.x));
        float2 b1 = __half22float2(*reinterpret_cast<__half2*>(&h1.y));
        acc.x += a0.x * v0; acc.y += a0.y * v0;
        acc.z += b0.x * v0; acc.w += b0.y * v0;
        acc.x += a1.x * v1; acc.y += a1.y * v1;
        acc.z += b1.x * v1; acc.w += b1.y * v1;
    }
    if (i < e) {
        int2 e0 = g_edge[i];
        float v0 = __int_as_float(e0.y);
        uint2 h0 = *reinterpret_cast<const uint2*>(
            &g_supph[(size_t)e0.x * D + lane * 4]);
        float2 a0 = __half22float2(*reinterpret_cast<__half2*>(&h0.x));
        float2 b0 = __half22float2(*reinterpret_cast<__half2*>(&h0.y));
        acc.x += a0.x * v0; acc.y += a0.y * v0;
        acc.z += b0.x * v0; acc.w += b0.y * v0;
    }
    reinterpret_cast<float4*>(out)[(size_t)row * (D / 4) + lane] = acc;
}

// ---------------------------------------------------------------------------
// Launch.  Inputs: x, rows, cols, vals, W, b.  Output: f32 [N_NODES, D].
// Serial this round (clean per-phase attribution; overlap re-tested next).
// ---------------------------------------------------------------------------
extern "C" void kernel_launch(void* const* d_in, const int* in_sizes, int n_in,
                              void* d_out, int out_size) {
    const float* x    = (const float*)d_in[0];
    const int*   rows = (const int*)d_in[1];
    const int*   cols = (const int*)d_in[2];
    const float* vals = (const float*)d_in[3];
    const float* W    = (const float*)d_in[4];
    const float* b    = (const float*)d_in[5];
    float* out = (float*)d_out;

    __half* suph = nullptr;
    cudaGetSymbolAddress((void**)&suph, g_supph);

    zero_counts_kernel<<<(N_NODES + 255) / 256, 256>>>();
    hist_kernel<<<(N_EDGES + 255) / 256, 256>>>(rows);
    reduce_kernel<<<NB_SCAN, SCAN_BLK>>>();
    scan_sums_kernel<<<1, 256>>>();
    scan_block_kernel<<<NB_SCAN, SCAN_BLK>>>();
    fill_kernel<<<(N_EDGES + 255) / 256, 256>>>(rows, cols, vals);

    gemm_bias_kernel<<<(N_NODES + GR - 1) / GR, 256>>>(x, W, b, suph);

    {
        long long total_threads = (long long)N_NODES * 32;
        int blk = 256;
        int grid = (int)((total_threads + blk - 1) / blk);
        spmm_kernel<<<grid, blk>>>(out);
    }
}

// round 6
// speedup vs baseline: 1.3834x; 1.2973x over previous
#include <cuda_runtime.h>
#include <cuda_fp16.h>
#include <cstdint>

#define N_NODES 100000
#define N_EDGES 1600000
#define D 128          // D_IN == D_OUT == 128

#define SCAN_BLK 512
#define NB_SCAN ((N_NODES + SCAN_BLK - 1) / SCAN_BLK)   // 196

// ---- device-global scratch (allocation-free rule) ----
__device__ __half g_supph[(size_t)N_NODES * D];    // 25.6 MB (fp16 support)
__device__ int    g_counts[N_NODES];
__device__ int    g_rowstart[N_NODES + 1];
__device__ int    g_cur[N_NODES];
__device__ int    g_sums[NB_SCAN];
__device__ int    g_offsets[NB_SCAN];
__device__ int2   g_edge[N_EDGES];                 // 12.8 MB {col, val bits}

// ---------------------------------------------------------------------------
// 0) zero the per-row edge counters (every call / graph replay)
// ---------------------------------------------------------------------------
__global__ void zero_counts_kernel() {
    int i = blockIdx.x * blockDim.x + threadIdx.x;
    if (i < N_NODES) g_counts[i] = 0;
}

// ---------------------------------------------------------------------------
// 1) GEMM v4 (tensor cores, tf32): support = x @ W + b, stored fp16.
//    Block: 128 rows x 128 cols, 256 threads = 8 warps, warp tile 32x64.
//    mma.sync.aligned.m16n8k8.row.col.f32.tf32.tf32.f32, fp32 accumulate.
//    x and W staged to smem with cvt.rna.tf32 during staging.
//    Padding chosen so fragment LDS are conflict-free:
//      A: bank = 4*gid + tig (xs stride 36)   -> bijective on 0..31
//      B: bank = 8*tig + gid (ws stride 136)  -> bijective on 0..31
// ---------------------------------------------------------------------------
#define GR 128
#define KT 32
#define XS_S 36    // 32 + 4 pad
#define WS_S 136   // 128 + 8 pad

__device__ __forceinline__ unsigned f2tf32(float f) {
    unsigned u;
    asm("cvt.rna.tf32.f32 %0, %1;" : "=r"(u) : "f"(f));
    return u;
}

__device__ __forceinline__ void mma_tf32(float c[4], const unsigned a[4],
                                         const unsigned bb[2]) {
    asm volatile(
        "mma.sync.aligned.m16n8k8.row.col.f32.tf32.tf32.f32 "
        "{%0,%1,%2,%3}, {%4,%5,%6,%7}, {%8,%9}, {%0,%1,%2,%3};"
        : "+f"(c[0]), "+f"(c[1]), "+f"(c[2]), "+f"(c[3])
        : "r"(a[0]), "r"(a[1]), "r"(a[2]), "r"(a[3]),
          "r"(bb[0]), "r"(bb[1]));
}

__global__ __launch_bounds__(256, 2) void gemm_tc_kernel(
    const float* __restrict__ x, const float* __restrict__ W,
    const float* __restrict__ b, __half* __restrict__ suph) {
    __shared__ unsigned xs[GR][XS_S];   // x tile, tf32 bits  (18.4 KB)
    __shared__ unsigned ws[KT][WS_S];   // W tile, tf32 bits  (17.4 KB)

    const int tid  = threadIdx.x;
    const int lane = tid & 31;
    const int warp = tid >> 5;
    const int wr   = warp >> 1;         // warp row group 0..3 (32 rows each)
    const int wc   = warp & 1;          // warp col group 0..1 (64 cols each)
    const int gid  = lane >> 2;         // 0..7
    const int tig  = lane & 3;          // 0..3
    const int row0 = blockIdx.x * GR;

    float acc[2][8][4];
#pragma unroll
    for (int mi = 0; mi < 2; mi++)
#pragma unroll
        for (int ni = 0; ni < 8; ni++)
#pragma unroll
            for (int q = 0; q < 4; q++) acc[mi][ni][q] = 0.f;

    for (int kt = 0; kt < D; kt += KT) {
        __syncthreads();
        // stage x: 128 rows x 32 k, 16 elems/thread, coalesced reads
#pragma unroll
        for (int j = 0; j < 16; j++) {
            int idx = tid + j * 256;               // 0..4095
            int r = idx >> 5, k = idx & 31;
            int grow = row0 + r;
            float v = (grow < N_NODES) ? x[(size_t)grow * D + kt + k] : 0.f;
            xs[r][k] = f2tf32(v);
        }
        // stage W: 32 k x 128 c, float4 reads, uint4 stores (16B aligned)
#pragma unroll
        for (int j = 0; j < 4; j++) {
            int idx = tid + j * 256;               // float4 idx 0..1023
            int k = idx >> 5, c4 = idx & 31;
            float4 w = reinterpret_cast<const float4*>(
                &W[(size_t)(kt + k) * D])[c4];
            uint4 u = make_uint4(f2tf32(w.x), f2tf32(w.y),
                                 f2tf32(w.z), f2tf32(w.w));
            *reinterpret_cast<uint4*>(&ws[k][c4 * 4]) = u;
        }
        __syncthreads();

#pragma unroll
        for (int ks = 0; ks < 4; ks++) {           // 4 x k8 steps
            const int kb = ks * 8;
            unsigned a[2][4];
#pragma unroll
            for (int mi = 0; mi < 2; mi++) {
                const int r = wr * 32 + mi * 16 + gid;
                a[mi][0] = xs[r][kb + tig];
                a[mi][1] = xs[r + 8][kb + tig];
                a[mi][2] = xs[r][kb + tig + 4];
                a[mi][3] = xs[r + 8][kb + tig + 4];
            }
            unsigned bb[8][2];
#pragma unroll
            for (int ni = 0; ni < 8; ni++) {
                const int c = wc * 64 + ni * 8 + gid;
                bb[ni][0] = ws[kb + tig][c];
                bb[ni][1] = ws[kb + tig + 4][c];
            }
#pragma unroll
            for (int mi = 0; mi < 2; mi++)
#pragma unroll
                for (int ni = 0; ni < 8; ni++)
                    mma_tf32(acc[mi][ni], a[mi], bb[ni]);
        }
    }

    // epilogue: + bias, cvt fp16, half2 stores
#pragma unroll
    for (int mi = 0; mi < 2; mi++) {
#pragma unroll
        for (int ni = 0; ni < 8; ni++) {
            const int col = wc * 64 + ni * 8 + 2 * tig;
            const float b0 = b[col], b1 = b[col + 1];
            const int r0 = row0 + wr * 32 + mi * 16 + gid;
            const int r1 = r0 + 8;
            if (r0 < N_NODES) {
                __half2 h = __floats2half2_rn(acc[mi][ni][0] + b0,
                                              acc[mi][ni][1] + b1);
                *reinterpret_cast<__half2*>(&g_supph[(size_t)r0 * D + col]) = h;
            }
            if (r1 < N_NODES) {
                __half2 h = __floats2half2_rn(acc[mi][ni][2] + b0,
                                              acc[mi][ni][3] + b1);
                *reinterpret_cast<__half2*>(&g_supph[(size_t)r1 * D + col]) = h;
            }
        }
    }
    (void)suph;
}

// ---------------------------------------------------------------------------
// 2) histogram of destination rows
// ---------------------------------------------------------------------------
__global__ void hist_kernel(const int* __restrict__ rows) {
    int e = blockIdx.x * blockDim.x + threadIdx.x;
    if (e < N_EDGES) atomicAdd(&g_counts[rows[e]], 1);
}

// ---------------------------------------------------------------------------
// 3a) per-block reduction of counts
// ---------------------------------------------------------------------------
__global__ void reduce_kernel() {
    __shared__ int sh[SCAN_BLK];
    int g = blockIdx.x * SCAN_BLK + threadIdx.x;
    sh[threadIdx.x] = (g < N_NODES) ? g_counts[g] : 0;
    __syncthreads();
#pragma unroll
    for (int s = SCAN_BLK / 2; s > 0; s >>= 1) {
        if (threadIdx.x < s) sh[threadIdx.x] += sh[threadIdx.x + s];
        __syncthreads();
    }
    if (threadIdx.x == 0) g_sums[blockIdx.x] = sh[0];
}

// 3b) exclusive scan of the 196 block sums (single block, parallel)
__global__ void scan_sums_kernel() {
    __shared__ int sh[256];
    int t = threadIdx.x;
    int v = (t < NB_SCAN) ? g_sums[t] : 0;
    sh[t] = v;
    __syncthreads();
#pragma unroll
    for (int d = 1; d < 256; d <<= 1) {
        int tv = (t >= d) ? sh[t - d] : 0;
        __syncthreads();
        sh[t] += tv;
        __syncthreads();
    }
    if (t < NB_SCAN) g_offsets[t] = sh[t] - v;   // exclusive
}

// 3c) per-block exclusive scan + global offset -> row_start, cur
__global__ void scan_block_kernel() {
    __shared__ int sh[SCAN_BLK];
    int tid = threadIdx.x;
    int g = blockIdx.x * SCAN_BLK + tid;
    int v = (g < N_NODES) ? g_counts[g] : 0;
    sh[tid] = v;
    __syncthreads();
#pragma unroll
    for (int d = 1; d < SCAN_BLK; d <<= 1) {
        int t = (tid >= d) ? sh[tid - d] : 0;
        __syncthreads();
        sh[tid] += t;
        __syncthreads();
    }
    int incl = sh[tid];
    int excl = incl - v;
    int base = g_offsets[blockIdx.x];
    if (g < N_NODES) {
        int s = base + excl;
        g_rowstart[g] = s;
        g_cur[g] = s;
        if (g == N_NODES - 1) g_rowstart[N_NODES] = base + incl;
    }
}

// ---------------------------------------------------------------------------
// 4) scatter edges into CSR slots (packed {col, val} -> one 8B store)
// ---------------------------------------------------------------------------
__global__ void fill_kernel(const int* __restrict__ rows,
                            const int* __restrict__ cols,
                            const float* __restrict__ vals) {
    int e = blockIdx.x * blockDim.x + threadIdx.x;
    if (e < N_EDGES) {
        int r = rows[e];
        int pos = atomicAdd(&g_cur[r], 1);
        g_edge[pos] = make_int2(cols[e], __float_as_int(vals[e]));
    }
}

// ---------------------------------------------------------------------------
// 5) SpMM: one warp per output row, fp16 gathers (256B/row), fp32 accumulate,
//          single coalesced float4 store.
// ---------------------------------------------------------------------------
__global__ __launch_bounds__(256) void spmm_kernel(float* __restrict__ out) {
    const int row  = (blockIdx.x * blockDim.x + threadIdx.x) >> 5;
    const int lane = threadIdx.x & 31;
    if (row >= N_NODES) return;

    const int s = __ldg(&g_rowstart[row]);
    const int e = __ldg(&g_rowstart[row + 1]);

    float4 acc = make_float4(0.f, 0.f, 0.f, 0.f);

    int i = s;
    for (; i + 1 < e; i += 2) {
        int2 e0 = g_edge[i];
        int2 e1 = g_edge[i + 1];
        float v0 = __int_as_float(e0.y);
        float v1 = __int_as_float(e1.y);
        uint2 h0 = *reinterpret_cast<const uint2*>(
            &g_supph[(size_t)e0.x * D + lane * 4]);
        uint2 h1 = *reinterpret_cast<const uint2*>(
            &g_supph[(size_t)e1.x * D + lane * 4]);
        float2 a0 = __half22float2(*reinterpret_cast<__half2*>(&h0.x));
        float2 b0 = __half22float2(*reinterpret_cast<__half2*>(&h0.y));
        float2 a1 = __half22float2(*reinterpret_cast<__half2*>(&h1.x));
        float2 b1 = __half22float2(*reinterpret_cast<__half2*>(&h1.y));
        acc.x += a0.x * v0; acc.y += a0.y * v0;
        acc.z += b0.x * v0; acc.w += b0.y * v0;
        acc.x += a1.x * v1; acc.y += a1.y * v1;
        acc.z += b1.x * v1; acc.w += b1.y * v1;
    }
    if (i < e) {
        int2 e0 = g_edge[i];
        float v0 = __int_as_float(e0.y);
        uint2 h0 = *reinterpret_cast<const uint2*>(
            &g_supph[(size_t)e0.x * D + lane * 4]);
        float2 a0 = __half22float2(*reinterpret_cast<__half2*>(&h0.x));
        float2 b0 = __half22float2(*reinterpret_cast<__half2*>(&h0.y));
        acc.x += a0.x * v0; acc.y += a0.y * v0;
        acc.z += b0.x * v0; acc.w += b0.y * v0;
    }
    reinterpret_cast<float4*>(out)[(size_t)row * (D / 4) + lane] = acc;
}

// ---------------------------------------------------------------------------
// Launch.  Inputs: x, rows, cols, vals, W, b.  Output: f32 [N_NODES, D].
// Serial; GEMM placed at launch index 3 (the slot ncu has been sampling)
// so next round's profile captures it.
// ---------------------------------------------------------------------------
extern "C" void kernel_launch(void* const* d_in, const int* in_sizes, int n_in,
                              void* d_out, int out_size) {
    const float* x    = (const float*)d_in[0];
    const int*   rows = (const int*)d_in[1];
    const int*   cols = (const int*)d_in[2];
    const float* vals = (const float*)d_in[3];
    const float* W    = (const float*)d_in[4];
    const float* b    = (const float*)d_in[5];
    float* out = (float*)d_out;

    __half* suph = nullptr;
    cudaGetSymbolAddress((void**)&suph, g_supph);

    zero_counts_kernel<<<(N_NODES + 255) / 256, 256>>>();       // 0
    hist_kernel<<<(N_EDGES + 255) / 256, 256>>>(rows);          // 1
    reduce_kernel<<<NB_SCAN, SCAN_BLK>>>();                     // 2
    gemm_tc_kernel<<<(N_NODES + GR - 1) / GR, 256>>>(x, W, b, suph); // 3
    scan_sums_kernel<<<1, 256>>>();                             // 4
    scan_block_kernel<<<NB_SCAN, SCAN_BLK>>>();                 // 5
    fill_kernel<<<(N_EDGES + 255) / 256, 256>>>(rows, cols, vals); // 6

    {
        long long total_threads = (long long)N_NODES * 32;
        int blk = 256;
        int grid = (int)((total_threads + blk - 1) / blk);
        spmm_kernel<<<grid, blk>>>(out);                        // 7
    }
}

// round 7
// speedup vs baseline: 1.5184x; 1.0976x over previous
#include <cuda_runtime.h>
#include <cuda_fp16.h>
#include <cstdint>

#define N_NODES 100000
#define N_EDGES 1600000
#define D 128          // D_IN == D_OUT == 128

#define SCAN_BLK 512
#define NB_SCAN ((N_NODES + SCAN_BLK - 1) / SCAN_BLK)   // 196

// ---- device-global scratch (allocation-free rule) ----
__device__ __half g_supph[(size_t)N_NODES * D];    // 25.6 MB (fp16 support)
__device__ int    g_counts[N_NODES];
__device__ int    g_rowstart[N_NODES + 1];
__device__ int    g_cur[N_NODES];
__device__ int    g_sums[NB_SCAN];
__device__ int    g_offsets[NB_SCAN];
__device__ int2   g_edge[N_EDGES];                 // 12.8 MB {col, val bits}

// ---- side stream + events for fork-join under graph capture.
// Created once in a global constructor (before the harness's first memory
// checkpoint; no per-call resource creation).
struct StreamInit {
    cudaStream_t s2;
    cudaEvent_t ev_fork, ev_join;
    StreamInit() {
        cudaStreamCreateWithFlags(&s2, cudaStreamNonBlocking);
        cudaEventCreateWithFlags(&ev_fork, cudaEventDisableTiming);
        cudaEventCreateWithFlags(&ev_join, cudaEventDisableTiming);
    }
};
static StreamInit g_si;

// ---------------------------------------------------------------------------
// 0) zero the per-row edge counters (every call / graph replay)
// ---------------------------------------------------------------------------
__global__ void zero_counts_kernel() {
    int i = blockIdx.x * blockDim.x + threadIdx.x;
    if (i < N_NODES) g_counts[i] = 0;
}

// ---------------------------------------------------------------------------
// 1) GEMM (tensor cores, tf32): support = x @ W + b, stored fp16.
//    UNCHANGED from R6-measured kernel (41 us) to isolate the overlap change.
// ---------------------------------------------------------------------------
#define GR 128
#define KT 32
#define XS_S 36    // 32 + 4 pad
#define WS_S 136   // 128 + 8 pad

__device__ __forceinline__ unsigned f2tf32(float f) {
    unsigned u;
    asm("cvt.rna.tf32.f32 %0, %1;" : "=r"(u) : "f"(f));
    return u;
}

__device__ __forceinline__ void mma_tf32(float c[4], const unsigned a[4],
                                         const unsigned bb[2]) {
    asm volatile(
        "mma.sync.aligned.m16n8k8.row.col.f32.tf32.tf32.f32 "
        "{%0,%1,%2,%3}, {%4,%5,%6,%7}, {%8,%9}, {%0,%1,%2,%3};"
        : "+f"(c[0]), "+f"(c[1]), "+f"(c[2]), "+f"(c[3])
        : "r"(a[0]), "r"(a[1]), "r"(a[2]), "r"(a[3]),
          "r"(bb[0]), "r"(bb[1]));
}

__global__ __launch_bounds__(256, 2) void gemm_tc_kernel(
    const float* __restrict__ x, const float* __restrict__ W,
    const float* __restrict__ b, __half* __restrict__ suph) {
    __shared__ unsigned xs[GR][XS_S];
    __shared__ unsigned ws[KT][WS_S];

    const int tid  = threadIdx.x;
    const int lane = tid & 31;
    const int warp = tid >> 5;
    const int wr   = warp >> 1;
    const int wc   = warp & 1;
    const int gid  = lane >> 2;
    const int tig  = lane & 3;
    const int row0 = blockIdx.x * GR;

    float acc[2][8][4];
#pragma unroll
    for (int mi = 0; mi < 2; mi++)
#pragma unroll
        for (int ni = 0; ni < 8; ni++)
#pragma unroll
            for (int q = 0; q < 4; q++) acc[mi][ni][q] = 0.f;

    for (int kt = 0; kt < D; kt += KT) {
        __syncthreads();
#pragma unroll
        for (int j = 0; j < 16; j++) {
            int idx = tid + j * 256;
            int r = idx >> 5, k = idx & 31;
            int grow = row0 + r;
            float v = (grow < N_NODES) ? x[(size_t)grow * D + kt + k] : 0.f;
            xs[r][k] = f2tf32(v);
        }
#pragma unroll
        for (int j = 0; j < 4; j++) {
            int idx = tid + j * 256;
            int k = idx >> 5, c4 = idx & 31;
            float4 w = reinterpret_cast<const float4*>(
                &W[(size_t)(kt + k) * D])[c4];
            uint4 u = make_uint4(f2tf32(w.x), f2tf32(w.y),
                                 f2tf32(w.z), f2tf32(w.w));
            *reinterpret_cast<uint4*>(&ws[k][c4 * 4]) = u;
        }
        __syncthreads();

#pragma unroll
        for (int ks = 0; ks < 4; ks++) {
            const int kb = ks * 8;
            unsigned a[2][4];
#pragma unroll
            for (int mi = 0; mi < 2; mi++) {
                const int r = wr * 32 + mi * 16 + gid;
                a[mi][0] = xs[r][kb + tig];
                a[mi][1] = xs[r + 8][kb + tig];
                a[mi][2] = xs[r][kb + tig + 4];
                a[mi][3] = xs[r + 8][kb + tig + 4];
            }
            unsigned bb[8][2];
#pragma unroll
            for (int ni = 0; ni < 8; ni++) {
                const int c = wc * 64 + ni * 8 + gid;
                bb[ni][0] = ws[kb + tig][c];
                bb[ni][1] = ws[kb + tig + 4][c];
            }
#pragma unroll
            for (int mi = 0; mi < 2; mi++)
#pragma unroll
                for (int ni = 0; ni < 8; ni++)
                    mma_tf32(acc[mi][ni], a[mi], bb[ni]);
        }
    }

#pragma unroll
    for (int mi = 0; mi < 2; mi++) {
#pragma unroll
        for (int ni = 0; ni < 8; ni++) {
            const int col = wc * 64 + ni * 8 + 2 * tig;
            const float b0 = b[col], b1 = b[col + 1];
            const int r0 = row0 + wr * 32 + mi * 16 + gid;
            const int r1 = r0 + 8;
            if (r0 < N_NODES) {
                __half2 h = __floats2half2_rn(acc[mi][ni][0] + b0,
                                              acc[mi][ni][1] + b1);
                *reinterpret_cast<__half2*>(&g_supph[(size_t)r0 * D + col]) = h;
            }
            if (r1 < N_NODES) {
                __half2 h = __floats2half2_rn(acc[mi][ni][2] + b0,
                                              acc[mi][ni][3] + b1);
                *reinterpret_cast<__half2*>(&g_supph[(size_t)r1 * D + col]) = h;
            }
        }
    }
    (void)suph;
}

// ---------------------------------------------------------------------------
// 2) histogram of destination rows
// ---------------------------------------------------------------------------
__global__ void hist_kernel(const int* __restrict__ rows) {
    int e = blockIdx.x * blockDim.x + threadIdx.x;
    if (e < N_EDGES) atomicAdd(&g_counts[rows[e]], 1);
}

// ---------------------------------------------------------------------------
// 3a) per-block reduction of counts
// ---------------------------------------------------------------------------
__global__ void reduce_kernel() {
    __shared__ int sh[SCAN_BLK];
    int g = blockIdx.x * SCAN_BLK + threadIdx.x;
    sh[threadIdx.x] = (g < N_NODES) ? g_counts[g] : 0;
    __syncthreads();
#pragma unroll
    for (int s = SCAN_BLK / 2; s > 0; s >>= 1) {
        if (threadIdx.x < s) sh[threadIdx.x] += sh[threadIdx.x + s];
        __syncthreads();
    }
    if (threadIdx.x == 0) g_sums[blockIdx.x] = sh[0];
}

// 3b) exclusive scan of the 196 block sums (single block, parallel)
__global__ void scan_sums_kernel() {
    __shared__ int sh[256];
    int t = threadIdx.x;
    int v = (t < NB_SCAN) ? g_sums[t] : 0;
    sh[t] = v;
    __syncthreads();
#pragma unroll
    for (int d = 1; d < 256; d <<= 1) {
        int tv = (t >= d) ? sh[t - d] : 0;
        __syncthreads();
        sh[t] += tv;
        __syncthreads();
    }
    if (t < NB_SCAN) g_offsets[t] = sh[t] - v;   // exclusive
}

// 3c) per-block exclusive scan + global offset -> row_start, cur
__global__ void scan_block_kernel() {
    __shared__ int sh[SCAN_BLK];
    int tid = threadIdx.x;
    int g = blockIdx.x * SCAN_BLK + tid;
    int v = (g < N_NODES) ? g_counts[g] : 0;
    sh[tid] = v;
    __syncthreads();
#pragma unroll
    for (int d = 1; d < SCAN_BLK; d <<= 1) {
        int t = (tid >= d) ? sh[tid - d] : 0;
        __syncthreads();
        sh[tid] += t;
        __syncthreads();
    }
    int incl = sh[tid];
    int excl = incl - v;
    int base = g_offsets[blockIdx.x];
    if (g < N_NODES) {
        int s = base + excl;
        g_rowstart[g] = s;
        g_cur[g] = s;
        if (g == N_NODES - 1) g_rowstart[N_NODES] = base + incl;
    }
}

// ---------------------------------------------------------------------------
// 4) scatter edges into CSR slots (packed {col, val} -> one 8B store)
// ---------------------------------------------------------------------------
__global__ void fill_kernel(const int* __restrict__ rows,
                            const int* __restrict__ cols,
                            const float* __restrict__ vals) {
    int e = blockIdx.x * blockDim.x + threadIdx.x;
    if (e < N_EDGES) {
        int r = rows[e];
        int pos = atomicAdd(&g_cur[r], 1);
        g_edge[pos] = make_int2(cols[e], __float_as_int(vals[e]));
    }
}

// ---------------------------------------------------------------------------
// 5) SpMM: one warp per output row, fp16 gathers (256B/row), fp32 accumulate,
//          single coalesced float4 store.
// ---------------------------------------------------------------------------
__global__ __launch_bounds__(256) void spmm_kernel(float* __restrict__ out) {
    const int row  = (blockIdx.x * blockDim.x + threadIdx.x) >> 5;
    const int lane = threadIdx.x & 31;
    if (row >= N_NODES) return;

    const int s = __ldg(&g_rowstart[row]);
    const int e = __ldg(&g_rowstart[row + 1]);

    float4 acc = make_float4(0.f, 0.f, 0.f, 0.f);

    int i = s;
    for (; i + 1 < e; i += 2) {
        int2 e0 = g_edge[i];
        int2 e1 = g_edge[i + 1];
        float v0 = __int_as_float(e0.y);
        float v1 = __int_as_float(e1.y);
        uint2 h0 = *reinterpret_cast<const uint2*>(
            &g_supph[(size_t)e0.x * D + lane * 4]);
        uint2 h1 = *reinterpret_cast<const uint2*>(
            &g_supph[(size_t)e1.x * D + lane * 4]);
        float2 a0 = __half22float2(*reinterpret_cast<__half2*>(&h0.x));
        float2 b0 = __half22float2(*reinterpret_cast<__half2*>(&h0.y));
        float2 a1 = __half22float2(*reinterpret_cast<__half2*>(&h1.x));
        float2 b1 = __half22float2(*reinterpret_cast<__half2*>(&h1.y));
        acc.x += a0.x * v0; acc.y += a0.y * v0;
        acc.z += b0.x * v0; acc.w += b0.y * v0;
        acc.x += a1.x * v1; acc.y += a1.y * v1;
        acc.z += b1.x * v1; acc.w += b1.y * v1;
    }
    if (i < e) {
        int2 e0 = g_edge[i];
        float v0 = __int_as_float(e0.y);
        uint2 h0 = *reinterpret_cast<const uint2*>(
            &g_supph[(size_t)e0.x * D + lane * 4]);
        float2 a0 = __half22float2(*reinterpret_cast<__half2*>(&h0.x));
        float2 b0 = __half22float2(*reinterpret_cast<__half2*>(&h0.y));
        acc.x += a0.x * v0; acc.y += a0.y * v0;
        acc.z += b0.x * v0; acc.w += b0.y * v0;
    }
    reinterpret_cast<float4*>(out)[(size_t)row * (D / 4) + lane] = acc;
}

// ---------------------------------------------------------------------------
// Launch.  Inputs: x, rows, cols, vals, W, b.  Output: f32 [N_NODES, D].
// Fork-join: CSR build chain on side stream || GEMM on capture stream;
// join, then SpMM. GEMM is byte-identical to the R6-measured one, so this
// round isolates the overlap's true cost/benefit.
// ---------------------------------------------------------------------------
extern "C" void kernel_launch(void* const* d_in, const int* in_sizes, int n_in,
                              void* d_out, int out_size) {
    const float* x    = (const float*)d_in[0];
    const int*   rows = (const int*)d_in[1];
    const int*   cols = (const int*)d_in[2];
    const float* vals = (const float*)d_in[3];
    const float* W    = (const float*)d_in[4];
    const float* b    = (const float*)d_in[5];
    float* out = (float*)d_out;

    __half* suph = nullptr;
    cudaGetSymbolAddress((void**)&suph, g_supph);

    // fork side stream off the (captured) default stream
    cudaEventRecord(g_si.ev_fork, 0);
    cudaStreamWaitEvent(g_si.s2, g_si.ev_fork, 0);

    // --- CSR build chain on side stream ---
    zero_counts_kernel<<<(N_NODES + 255) / 256, 256, 0, g_si.s2>>>();
    hist_kernel<<<(N_EDGES + 255) / 256, 256, 0, g_si.s2>>>(rows);
    reduce_kernel<<<NB_SCAN, SCAN_BLK, 0, g_si.s2>>>();
    scan_sums_kernel<<<1, 256, 0, g_si.s2>>>();
    scan_block_kernel<<<NB_SCAN, SCAN_BLK, 0, g_si.s2>>>();
    fill_kernel<<<(N_EDGES + 255) / 256, 256, 0, g_si.s2>>>(rows, cols, vals);
    cudaEventRecord(g_si.ev_join, g_si.s2);

    // --- GEMM on the capture stream (overlaps the chain) ---
    gemm_tc_kernel<<<(N_NODES + GR - 1) / GR, 256>>>(x, W, b, suph);

    // --- join, then SpMM ---
    cudaStreamWaitEvent(0, g_si.ev_join, 0);
    {
        long long total_threads = (long long)N_NODES * 32;
        int blk = 256;
        int grid = (int)((total_threads + blk - 1) / blk);
        spmm_kernel<<<grid, blk>>>(out);
    }
}

// round 8
// speedup vs baseline: 1.5715x; 1.0350x over previous
#include <cuda_runtime.h>
#include <cuda_fp16.h>
#include <cstdint>

#define N_NODES 100000
#define N_EDGES 1600000
#define D 128          // D_IN == D_OUT == 128

#define SCAN_BLK 512
#define NB_SCAN ((N_NODES + SCAN_BLK - 1) / SCAN_BLK)   // 196

// ---- device-global scratch (allocation-free rule) ----
__device__ __half g_supph[(size_t)N_NODES * D];    // 25.6 MB (fp16 support)
__device__ int    g_counts[N_NODES];               // zero at load; re-zeroed by fill
__device__ int    g_rowstart[N_NODES + 1];
__device__ int    g_cur[N_NODES];
__device__ unsigned long long g_status[NB_SCAN];   // lookback flags; re-zeroed by fill
__device__ int2   g_edge[N_EDGES];                 // 12.8 MB {col, val bits}

#define FLG_A (1ull << 40)
#define FLG_P (2ull << 40)
#define VAL_MASK 0xFFFFFFFFull

// ---- GEMM tiling ----
#define GR 128
#define KT 32
#define XS_S 36    // 32 + 4 pad  (A fragment banks: 4*gid+tig, bijective)
#define WS_S 136   // 128 + 8 pad (B fragment banks: 8*tig+gid, bijective)
#define XS_ELEMS (GR * XS_S)          // 4608 floats per stage
#define WS_ELEMS (KT * WS_S)          // 4352 floats per stage
#define STAGE_ELEMS (XS_ELEMS + WS_ELEMS)
#define GEMM_SMEM_BYTES (2 * STAGE_ELEMS * 4)   // 71680 B

__global__ void gemm_tc_kernel(const float*, const float*, const float*);

// ---- side stream + events + func attribute, once per process ----
struct StreamInit {
    cudaStream_t s2;
    cudaEvent_t ev_fork, ev_join;
    StreamInit() {
        cudaStreamCreateWithFlags(&s2, cudaStreamNonBlocking);
        cudaEventCreateWithFlags(&ev_fork, cudaEventDisableTiming);
        cudaEventCreateWithFlags(&ev_join, cudaEventDisableTiming);
        cudaFuncSetAttribute(gemm_tc_kernel,
                             cudaFuncAttributeMaxDynamicSharedMemorySize,
                             GEMM_SMEM_BYTES);
    }
};
static StreamInit g_si;

// ---------------------------------------------------------------------------
// GEMM (tf32 tensor cores, 2-stage cp.async pipeline): support = x@W+b, fp16.
// Block 128x128, 8 warps, warp tile 32x64. Raw fp32 tiles staged via
// cp.async.cg (no register staging); cvt.rna.tf32 at fragment-load time.
// ---------------------------------------------------------------------------
__device__ __forceinline__ unsigned f2tf32(float f) {
    unsigned u;
    asm("cvt.rna.tf32.f32 %0, %1;" : "=r"(u) : "f"(f));
    return u;
}

__device__ __forceinline__ void mma_tf32(float c[4], const unsigned a[4],
                                         const unsigned bb[2]) {
    asm volatile(
        "mma.sync.aligned.m16n8k8.row.col.f32.tf32.tf32.f32 "
        "{%0,%1,%2,%3}, {%4,%5,%6,%7}, {%8,%9}, {%0,%1,%2,%3};"
        : "+f"(c[0]), "+f"(c[1]), "+f"(c[2]), "+f"(c[3])
        : "r"(a[0]), "r"(a[1]), "r"(a[2]), "r"(a[3]),
          "r"(bb[0]), "r"(bb[1]));
}

__device__ __forceinline__ void cpa16(void* smem_dst, const void* gmem_src,
                                      bool pred) {
    unsigned sa = (unsigned)__cvta_generic_to_shared(smem_dst);
    int sz = pred ? 16 : 0;
    asm volatile("cp.async.cg.shared.global [%0], [%1], 16, %2;"
                 :: "r"(sa), "l"(gmem_src), "r"(sz));
}

__global__ __launch_bounds__(256, 2) void gemm_tc_kernel(
    const float* __restrict__ x, const float* __restrict__ W,
    const float* __restrict__ b) {
    extern __shared__ float smem[];
    // layout: [stage][xs GR*XS_S][ws KT*WS_S]
#define XS(st, r, k) smem[(st) * STAGE_ELEMS + (r) * XS_S + (k)]
#define WS(st, k, c) smem[(st) * STAGE_ELEMS + XS_ELEMS + (k) * WS_S + (c)]

    const int tid  = threadIdx.x;
    const int lane = tid & 31;
    const int warp = tid >> 5;
    const int wr   = warp >> 1;
    const int wc   = warp & 1;
    const int gid  = lane >> 2;
    const int tig  = lane & 3;
    const int row0 = blockIdx.x * GR;

    // prefetch one k-tile into stage st
    auto prefetch = [&](int st, int kt) {
        // x tile: 128 rows x 32 cols = 1024 x 16B chunks
#pragma unroll
        for (int j = 0; j < 4; j++) {
            int id = tid + j * 256;
            int r = id >> 3, c16 = id & 7;
            int grow = row0 + r;
            bool ok = grow < N_NODES;
            const float* src = x + (size_t)(ok ? grow : 0) * D + kt + c16 * 4;
            cpa16(&XS(st, r, c16 * 4), src, ok);
        }
        // W tile: 32 rows x 128 cols = 1024 x 16B chunks
#pragma unroll
        for (int j = 0; j < 4; j++) {
            int id = tid + j * 256;
            int k = id >> 5, c16 = id & 31;
            cpa16(&WS(st, k, c16 * 4), W + (size_t)(kt + k) * D + c16 * 4, true);
        }
        asm volatile("cp.async.commit_group;");
    };

    float acc[2][8][4];
#pragma unroll
    for (int mi = 0; mi < 2; mi++)
#pragma unroll
        for (int ni = 0; ni < 8; ni++)
#pragma unroll
            for (int q = 0; q < 4; q++) acc[mi][ni][q] = 0.f;

    prefetch(0, 0);

#pragma unroll
    for (int kti = 0; kti < 4; kti++) {
        if (kti < 3) {
            prefetch((kti + 1) & 1, (kti + 1) * KT);
            asm volatile("cp.async.wait_group 1;" ::: "memory");
        } else {
            asm volatile("cp.async.wait_group 0;" ::: "memory");
        }
        __syncthreads();

        const int st = kti & 1;
#pragma unroll
        for (int ks = 0; ks < 4; ks++) {
            const int kb = ks * 8;
            unsigned a[2][4];
#pragma unroll
            for (int mi = 0; mi < 2; mi++) {
                const int r = wr * 32 + mi * 16 + gid;
                a[mi][0] = f2tf32(XS(st, r, kb + tig));
                a[mi][1] = f2tf32(XS(st, r + 8, kb + tig));
                a[mi][2] = f2tf32(XS(st, r, kb + tig + 4));
                a[mi][3] = f2tf32(XS(st, r + 8, kb + tig + 4));
            }
            unsigned bb[8][2];
#pragma unroll
            for (int ni = 0; ni < 8; ni++) {
                const int c = wc * 64 + ni * 8 + gid;
                bb[ni][0] = f2tf32(WS(st, kb + tig, c));
                bb[ni][1] = f2tf32(WS(st, kb + tig + 4, c));
            }
#pragma unroll
            for (int mi = 0; mi < 2; mi++)
#pragma unroll
                for (int ni = 0; ni < 8; ni++)
                    mma_tf32(acc[mi][ni], a[mi], bb[ni]);
        }
        __syncthreads();   // protect stage st before it is overwritten
    }

    // epilogue: + bias, cvt fp16, half2 stores
#pragma unroll
    for (int mi = 0; mi < 2; mi++) {
#pragma unroll
        for (int ni = 0; ni < 8; ni++) {
            const int col = wc * 64 + ni * 8 + 2 * tig;
            const float b0 = b[col], b1 = b[col + 1];
            const int r0 = row0 + wr * 32 + mi * 16 + gid;
            const int r1 = r0 + 8;
            if (r0 < N_NODES) {
                __half2 h = __floats2half2_rn(acc[mi][ni][0] + b0,
                                              acc[mi][ni][1] + b1);
                *reinterpret_cast<__half2*>(&g_supph[(size_t)r0 * D + col]) = h;
            }
            if (r1 < N_NODES) {
                __half2 h = __floats2half2_rn(acc[mi][ni][2] + b0,
                                              acc[mi][ni][3] + b1);
                *reinterpret_cast<__half2*>(&g_supph[(size_t)r1 * D + col]) = h;
            }
        }
    }
#undef XS
#undef WS
}

// ---------------------------------------------------------------------------
// CSR chain (3 kernels): hist -> lookback scan -> fill(+cleanup)
// g_counts / g_status are zero at process start and re-zeroed by fill,
// so every call sees the same initial state (deterministic, no guards).
// ---------------------------------------------------------------------------
__global__ void hist_kernel(const int* __restrict__ rows) {
    int e = blockIdx.x * blockDim.x + threadIdx.x;
    if (e < N_EDGES) atomicAdd(&g_counts[rows[e]], 1);
}

__global__ void scan_lookback_kernel() {
    __shared__ int sh[SCAN_BLK];
    __shared__ int s_base;
    const int bkt = blockIdx.x;
    const int tid = threadIdx.x;
    const int g = bkt * SCAN_BLK + tid;
    int v = (g < N_NODES) ? g_counts[g] : 0;
    sh[tid] = v;
    __syncthreads();
#pragma unroll
    for (int d = 1; d < SCAN_BLK; d <<= 1) {
        int t = (tid >= d) ? sh[tid - d] : 0;
        __syncthreads();
        sh[tid] += t;
        __syncthreads();
    }
    const int incl = sh[tid];
    const int total = sh[SCAN_BLK - 1];

    if (tid == 0) {
        if (bkt == 0) {
            atomicExch(&g_status[0], FLG_P | (unsigned long long)total);
            s_base = 0;
        } else {
            atomicExch(&g_status[bkt], FLG_A | (unsigned long long)total);
            long long run = 0;
            int p = bkt - 1;
            while (true) {
                unsigned long long s = atomicAdd(&g_status[p], 0ull);
                if (s & (FLG_A | FLG_P)) {
                    run += (long long)(s & VAL_MASK);
                    if (s & FLG_P) break;
                    p--;
                }
            }
            atomicExch(&g_status[bkt],
                       FLG_P | (unsigned long long)(run + total));
            s_base = (int)run;
        }
    }
    __syncthreads();

    const int base = s_base;
    if (g < N_NODES) {
        int st = base + incl - v;     // exclusive
        g_rowstart[g] = st;
        g_cur[g] = st;
        if (g == N_NODES - 1) g_rowstart[N_NODES] = base + incl;
    }
}

__global__ void fill_kernel(const int* __restrict__ rows,
                            const int* __restrict__ cols,
                            const float* __restrict__ vals) {
    int e = blockIdx.x * blockDim.x + threadIdx.x;
    if (e < N_EDGES) {
        int r = rows[e];
        int pos = atomicAdd(&g_cur[r], 1);
        g_edge[pos] = make_int2(cols[e], __float_as_int(vals[e]));
    }
    // cleanup for the next call (deterministic post-state)
    if (e < N_NODES) g_counts[e] = 0;
    if (e < NB_SCAN) g_status[e] = 0ull;
}

// ---------------------------------------------------------------------------
// SpMM: one warp per output row, fp16 gathers (256B/row), fp32 accumulate,
//       single coalesced float4 store.
// ---------------------------------------------------------------------------
__global__ __launch_bounds__(256) void spmm_kernel(float* __restrict__ out) {
    const int row  = (blockIdx.x * blockDim.x + threadIdx.x) >> 5;
    const int lane = threadIdx.x & 31;
    if (row >= N_NODES) return;

    const int s = __ldg(&g_rowstart[row]);
    const int e = __ldg(&g_rowstart[row + 1]);

    float4 acc = make_float4(0.f, 0.f, 0.f, 0.f);

    int i = s;
    for (; i + 1 < e; i += 2) {
        int2 e0 = g_edge[i];
        int2 e1 = g_edge[i + 1];
        float v0 = __int_as_float(e0.y);
        float v1 = __int_as_float(e1.y);
        uint2 h0 = *reinterpret_cast<const uint2*>(
            &g_supph[(size_t)e0.x * D + lane * 4]);
        uint2 h1 = *reinterpret_cast<const uint2*>(
            &g_supph[(size_t)e1.x * D + lane * 4]);
        float2 a0 = __half22float2(*reinterpret_cast<__half2*>(&h0.x));
        float2 b0 = __half22float2(*reinterpret_cast<__half2*>(&h0.y));
        float2 a1 = __half22float2(*reinterpret_cast<__half2*>(&h1.x));
        float2 b1 = __half22float2(*reinterpret_cast<__half2*>(&h1.y));
        acc.x += a0.x * v0; acc.y += a0.y * v0;
        acc.z += b0.x * v0; acc.w += b0.y * v0;
        acc.x += a1.x * v1; acc.y += a1.y * v1;
        acc.z += b1.x * v1; acc.w += b1.y * v1;
    }
    if (i < e) {
        int2 e0 = g_edge[i];
        float v0 = __int_as_float(e0.y);
        uint2 h0 = *reinterpret_cast<const uint2*>(
            &g_supph[(size_t)e0.x * D + lane * 4]);
        float2 a0 = __half22float2(*reinterpret_cast<__half2*>(&h0.x));
        float2 b0 = __half22float2(*reinterpret_cast<__half2*>(&h0.y));
        acc.x += a0.x * v0; acc.y += a0.y * v0;
        acc.z += b0.x * v0; acc.w += b0.y * v0;
    }
    reinterpret_cast<float4*>(out)[(size_t)row * (D / 4) + lane] = acc;
}

// ---------------------------------------------------------------------------
// Launch. Inputs: x, rows, cols, vals, W, b.  Output: f32 [N_NODES, D].
// Fork-join: 3-kernel CSR chain on side stream || pipelined GEMM on capture
// stream; join; SpMM.
// ---------------------------------------------------------------------------
extern "C" void kernel_launch(void* const* d_in, const int* in_sizes, int n_in,
                              void* d_out, int out_size) {
    const float* x    = (const float*)d_in[0];
    const int*   rows = (const int*)d_in[1];
    const int*   cols = (const int*)d_in[2];
    const float* vals = (const float*)d_in[3];
    const float* W    = (const float*)d_in[4];
    const float* b    = (const float*)d_in[5];
    float* out = (float*)d_out;

    // fork side stream off the (captured) default stream
    cudaEventRecord(g_si.ev_fork, 0);
    cudaStreamWaitEvent(g_si.s2, g_si.ev_fork, 0);

    // --- CSR build chain on side stream (3 kernels) ---
    hist_kernel<<<(N_EDGES + 255) / 256, 256, 0, g_si.s2>>>(rows);
    scan_lookback_kernel<<<NB_SCAN, SCAN_BLK, 0, g_si.s2>>>();
    fill_kernel<<<(N_EDGES + 255) / 256, 256, 0, g_si.s2>>>(rows, cols, vals);
    cudaEventRecord(g_si.ev_join, g_si.s2);

    // --- GEMM on the capture stream (overlaps the chain) ---
    gemm_tc_kernel<<<(N_NODES + GR - 1) / GR, 256, GEMM_SMEM_BYTES>>>(x, W, b);

    // --- join, then SpMM ---
    cudaStreamWaitEvent(0, g_si.ev_join, 0);
    {
        long long total_threads = (long long)N_NODES * 32;
        int blk = 256;
        int grid = (int)((total_threads + blk - 1) / blk);
        spmm_kernel<<<grid, blk>>>(out);
    }
}